// round 4
// baseline (speedup 1.0000x reference)
#include <cuda_runtime.h>
#include <math.h>

#define S_DIM   32768          // W*H*Z = 32*32*32
#define SH_DIM  16384          // pooled spatial (z/2)
#define C_DIM   256
#define CI_DIM  128
#define BATCH   4

// ---------------- scratch (device globals: no runtime allocation) ----------------
__device__ float d_Wt1[256 * 384];          // transposed stacked [g;theta;phi] weights: [c][o]
__device__ float d_Bs1[384];                // stacked biases
__device__ float d_Wt2[128 * 256];          // transposed w_w: [ci][co]
__device__ float d_th [BATCH * CI_DIM * S_DIM];    // theta(x), full z
__device__ float d_gp [BATCH * CI_DIM * SH_DIM];   // g(x) pooled
__device__ float d_php[BATCH * CI_DIM * SH_DIM];   // phi(x) pooled
__device__ float d_y  [BATCH * CI_DIM * S_DIM];    // attention output
__device__ float d_wy [BATCH * C_DIM  * S_DIM];    // W conv output
__device__ float d_scale[256];
__device__ float d_shift[256];

// ---------------- packed f32x2 helpers (2x fp32 FMA throughput on sm_103a) -------
__device__ __forceinline__ unsigned long long pk2(float x, float y) {
    unsigned long long r;
    asm("mov.b64 %0, {%1,%2};" : "=l"(r) : "f"(x), "f"(y));
    return r;
}
__device__ __forceinline__ void fma2(unsigned long long& d, unsigned long long a, unsigned long long b) {
    asm("fma.rn.f32x2 %0, %1, %2, %0;" : "+l"(d) : "l"(a), "l"(b));
}
__device__ __forceinline__ float2 up2(unsigned long long v) {
    float2 f;
    asm("mov.b64 {%0,%1}, %2;" : "=f"(f.x), "=f"(f.y) : "l"(v));
    return f;
}

// ---------------- prep: transpose weights for coalesced GEMM loads ----------------
__global__ void prep_kernel(const float* __restrict__ g_w,  const float* __restrict__ th_w,
                            const float* __restrict__ ph_w, const float* __restrict__ g_b,
                            const float* __restrict__ th_b, const float* __restrict__ ph_b,
                            const float* __restrict__ w_w) {
    int i = blockIdx.x * 256 + threadIdx.x;
    if (i < 98304) {                         // Wt1[c*384 + o] = W_o[o%128][c]
        int c = i / 384, o = i % 384;
        const float* src = (o < 128) ? g_w : (o < 256 ? th_w : ph_w);
        int oo = o & 127;
        d_Wt1[i] = src[oo * 256 + c];
    }
    if (i < 32768) {                         // Wt2[ci*256 + co] = w_w[co][ci]
        int ci = i / 256, co = i % 256;
        d_Wt2[i] = w_w[co * 128 + ci];
    }
    if (i < 384) {
        d_Bs1[i] = (i < 128) ? g_b[i] : (i < 256 ? th_b[i - 128] : ph_b[i - 256]);
    }
}

// ---------------- tiled GEMM: OUT(o,s) = sum_c Wt[c][o] * X[c][s] ------------------
// 128(o) x 128(s) tile, K-step 8, packed fma.rn.f32x2 accumulators
// (8 o-rows x 4 f32x2 s-pairs per thread).
// MODE 0: fused 3-conv on input x; blockIdx.x selects {g(pooled), theta(full), phi(pooled)}.
// MODE 1: W conv; X is the DEVICE-GLOBAL d_y (resolved in device code — never passed
//         from host; a __device__ symbol passed from host decays to the host shadow,
//         which GB300's ATS silently reads as zeros).
template <int KDIM, int LDW, int MODE>
__global__ void __launch_bounds__(256, 2)
gemm_kernel(const float* __restrict__ Xparam, const float* __restrict__ bias_g) {
    __shared__ __align__(16) float Ws[8][128];
    __shared__ __align__(16) float Xs[8][128];

    const int ot = blockIdx.x;
    const int st = blockIdx.y;
    const int b  = blockIdx.z;

    const float* Xbase = (MODE == 0) ? Xparam : (const float*)d_y;
    const float* X = Xbase + (size_t)b * KDIM * S_DIM + (size_t)st * 128;
    const float* W = (MODE == 0 ? d_Wt1 : d_Wt2) + ot * 128;

    const int tid = threadIdx.x;
    const int tx = tid & 15, ty = tid >> 4;
    const int lo = tid & 127;
    const int lk = (tid >> 7) * 4;

    unsigned long long acc[8][4];
#pragma unroll
    for (int i = 0; i < 8; i++)
#pragma unroll
        for (int j = 0; j < 4; j++) acc[i][j] = 0ull;

    float rw[4], rx[4];
#pragma unroll
    for (int r = 0; r < 4; r++) {
        rw[r] = W[(size_t)(lk + r) * LDW + lo];
        rx[r] = X[(size_t)(lk + r) * S_DIM + lo];
    }

    for (int k0 = 0; k0 < KDIM; k0 += 8) {
#pragma unroll
        for (int r = 0; r < 4; r++) {
            Ws[lk + r][lo] = rw[r];
            Xs[lk + r][lo] = rx[r];
        }
        __syncthreads();
        if (k0 + 8 < KDIM) {
#pragma unroll
            for (int r = 0; r < 4; r++) {
                rw[r] = W[(size_t)(k0 + 8 + lk + r) * LDW + lo];
                rx[r] = X[(size_t)(k0 + 8 + lk + r) * S_DIM + lo];
            }
        }
#pragma unroll
        for (int kk = 0; kk < 8; kk++) {
            // A fragment: 8 o-values, broadcast each into both f32x2 lanes
            float4 a0 = *(const float4*)&Ws[kk][ty * 8];
            float4 a1 = *(const float4*)&Ws[kk][ty * 8 + 4];
            unsigned long long a2[8];
            a2[0] = pk2(a0.x, a0.x); a2[1] = pk2(a0.y, a0.y);
            a2[2] = pk2(a0.z, a0.z); a2[3] = pk2(a0.w, a0.w);
            a2[4] = pk2(a1.x, a1.x); a2[5] = pk2(a1.y, a1.y);
            a2[6] = pk2(a1.z, a1.z); a2[7] = pk2(a1.w, a1.w);
            // B fragment: 8 consecutive s-values = 4 packed f32x2 (no repack needed)
            ulonglong2 bx0 = *(const ulonglong2*)&Xs[kk][tx * 8];
            ulonglong2 bx1 = *(const ulonglong2*)&Xs[kk][tx * 8 + 4];
            unsigned long long b2[4] = {bx0.x, bx0.y, bx1.x, bx1.y};
#pragma unroll
            for (int i = 0; i < 8; i++)
#pragma unroll
                for (int j = 0; j < 4; j++) fma2(acc[i][j], a2[i], b2[j]);
        }
        __syncthreads();
    }

    const int oo = ty * 8;
    const int ss = st * 128 + tx * 8;

    if (MODE == 0) {
#pragma unroll
        for (int i = 0; i < 8; i++) {
            float bia = d_Bs1[ot * 128 + oo + i];
            if (ot == 1) {  // theta: full z
                float* dst = d_th + ((size_t)(b * 128 + oo + i)) * S_DIM + ss;
#pragma unroll
                for (int j = 0; j < 4; j++) {
                    float2 v = up2(acc[i][j]);
                    v.x += bia; v.y += bia;
                    *(float2*)(dst + 2 * j) = v;
                }
            } else {        // g / phi: maxpool over consecutive z pairs (= f32x2 lanes)
                float* dst = (ot == 0 ? d_gp : d_php) +
                             ((size_t)(b * 128 + oo + i)) * SH_DIM + (ss >> 1);
#pragma unroll
                for (int j = 0; j < 4; j++) {
                    float2 v = up2(acc[i][j]);
                    dst[j] = fmaxf(v.x, v.y) + bia;
                }
            }
        }
    } else {
#pragma unroll
        for (int i = 0; i < 8; i++) {
            int o = ot * 128 + oo + i;
            float bia = bias_g[o];
            float* dst = d_wy + ((size_t)(b * 256 + o)) * S_DIM + ss;
#pragma unroll
            for (int j = 0; j < 4; j++) {
                float2 v = up2(acc[i][j]);
                v.x += bia; v.y += bia;
                *(float2*)(dst + 2 * j) = v;
            }
        }
    }
}

// ---------------- attention: per (b,w,h) group --------------------------------------
// f(z,y) = sum_c th[c][z]*ph[c][y]; softmax over y; y_out[c][z] = sum_y attn[z][y]*g[c][y]
__global__ void __launch_bounds__(128) attn_kernel() {
    __shared__ float th_s[128 * 32];
    __shared__ float ph_s[128 * 17];   // padded rows (conflict-free strided reads)
    __shared__ float g_s [128 * 17];
    __shared__ float f_s [32 * 16];

    const int grp = blockIdx.x;
    const int b   = grp >> 10;
    const int wh  = grp & 1023;
    const int tid = threadIdx.x;

    {   // theta tile: 128 rows x 32 floats
        const float* base = d_th + (size_t)(b * 128) * S_DIM + wh * 32;
        for (int i = tid; i < 1024; i += 128) {
            int c = i >> 3, q = i & 7;
            float4 v = *(const float4*)(base + (size_t)c * S_DIM + q * 4);
            *(float4*)&th_s[c * 32 + q * 4] = v;
        }
    }
    {   // pooled g / phi tiles: 128 rows x 16 floats (scalar STS into padded rows)
        const float* gb = d_gp  + (size_t)(b * 128) * SH_DIM + wh * 16;
        const float* pb = d_php + (size_t)(b * 128) * SH_DIM + wh * 16;
        for (int i = tid; i < 512; i += 128) {
            int c = i >> 2, q = (i & 3) * 4;
            float4 gv = *(const float4*)(gb + (size_t)c * SH_DIM + q);
            float4 pv = *(const float4*)(pb + (size_t)c * SH_DIM + q);
            int o = c * 17 + q;
            g_s[o + 0] = gv.x; g_s[o + 1] = gv.y; g_s[o + 2] = gv.z; g_s[o + 3] = gv.w;
            ph_s[o + 0] = pv.x; ph_s[o + 1] = pv.y; ph_s[o + 2] = pv.z; ph_s[o + 3] = pv.w;
        }
    }
    __syncthreads();

    {   // f: each thread computes 4 y values for one z
        const int z = tid >> 2, y0 = (tid & 3) * 4;
        float fv0 = 0.f, fv1 = 0.f, fv2 = 0.f, fv3 = 0.f;
#pragma unroll 8
        for (int c = 0; c < 128; c++) {
            float t = th_s[c * 32 + z];
            fv0 += t * ph_s[c * 17 + y0 + 0];
            fv1 += t * ph_s[c * 17 + y0 + 1];
            fv2 += t * ph_s[c * 17 + y0 + 2];
            fv3 += t * ph_s[c * 17 + y0 + 3];
        }
        f_s[z * 16 + y0 + 0] = fv0;
        f_s[z * 16 + y0 + 1] = fv1;
        f_s[z * 16 + y0 + 2] = fv2;
        f_s[z * 16 + y0 + 3] = fv3;
    }
    __syncthreads();

    if (tid < 32) {   // softmax over y per z-row
        int z = tid;
        float m = -1e30f;
#pragma unroll
        for (int y = 0; y < 16; y++) m = fmaxf(m, f_s[z * 16 + y]);
        float sum = 0.f;
#pragma unroll
        for (int y = 0; y < 16; y++) {
            float e = __expf(f_s[z * 16 + y] - m);
            f_s[z * 16 + y] = e;
            sum += e;
        }
        float inv = 1.f / sum;
#pragma unroll
        for (int y = 0; y < 16; y++) f_s[z * 16 + y] *= inv;
    }
    __syncthreads();

    {   // y_out: one channel row per thread
        const int c = tid;
        float yv[32];
#pragma unroll
        for (int z = 0; z < 32; z++) {
            float acc = 0.f;
#pragma unroll
            for (int y = 0; y < 16; y++) acc += f_s[z * 16 + y] * g_s[c * 17 + y];
            yv[z] = acc;
        }
        float* dst = d_y + (size_t)(b * 128 + c) * S_DIM + wh * 32;
#pragma unroll
        for (int q = 0; q < 8; q++)
            *(float4*)(dst + q * 4) = make_float4(yv[q * 4], yv[q * 4 + 1], yv[q * 4 + 2], yv[q * 4 + 3]);
    }
}

// ---------------- BN stats: per-channel mean/var over (b, spatial) -------------------
__global__ void __launch_bounds__(256) bn_stats(const float* __restrict__ gamma,
                                                const float* __restrict__ beta) {
    const int c = blockIdx.x;
    const int tid = threadIdx.x;
    float s = 0.f, s2 = 0.f;
    for (int i = tid; i < (BATCH * S_DIM) / 4; i += 256) {
        int e  = i * 4;
        int b  = e >> 15;
        int sp = e & (S_DIM - 1);
        float4 v = *(const float4*)&d_wy[((size_t)(b * 256 + c)) * S_DIM + sp];
        s  += v.x + v.y + v.z + v.w;
        s2 += v.x * v.x + v.y * v.y + v.z * v.z + v.w * v.w;
    }
    __shared__ float sh[256], sh2[256];
    sh[tid] = s; sh2[tid] = s2;
    __syncthreads();
    for (int off = 128; off > 0; off >>= 1) {
        if (tid < off) { sh[tid] += sh[tid + off]; sh2[tid] += sh2[tid + off]; }
        __syncthreads();
    }
    if (tid == 0) {
        float n = (float)(BATCH * S_DIM);
        float mean = sh[0] / n;
        float var  = sh2[0] / n - mean * mean;
        float inv  = rsqrtf(var + 1e-5f);
        float sc   = gamma[c] * inv;
        d_scale[c] = sc;
        d_shift[c] = beta[c] - mean * sc;
    }
}

// ---------------- BN apply + residual -------------------------------------------------
__global__ void __launch_bounds__(256) bn_apply(const float* __restrict__ x,
                                                float* __restrict__ out) {
    size_t i = (size_t)blockIdx.x * 256 + threadIdx.x;   // float4 index
    size_t e = i * 4;
    int c = (int)((e >> 15) & 255);
    float4 w  = *(const float4*)&d_wy[e];
    float4 xv = *(const float4*)(x + e);
    float sc = d_scale[c], sf = d_shift[c];
    float4 o;
    o.x = w.x * sc + sf + xv.x;
    o.y = w.y * sc + sf + xv.y;
    o.z = w.z * sc + sf + xv.z;
    o.w = w.w * sc + sf + xv.w;
    *(float4*)(out + e) = o;
}

// ---------------- launch ---------------------------------------------------------------
extern "C" void kernel_launch(void* const* d_in, const int* in_sizes, int n_in,
                              void* d_out, int out_size) {
    const float* x     = (const float*)d_in[0];
    const float* g_w   = (const float*)d_in[1];
    const float* g_b   = (const float*)d_in[2];
    const float* th_w  = (const float*)d_in[3];
    const float* th_b  = (const float*)d_in[4];
    const float* ph_w  = (const float*)d_in[5];
    const float* ph_b  = (const float*)d_in[6];
    const float* w_w   = (const float*)d_in[7];
    const float* w_b   = (const float*)d_in[8];
    const float* gamma = (const float*)d_in[9];
    const float* beta  = (const float*)d_in[10];
    float* out = (float*)d_out;

    prep_kernel<<<384, 256>>>(g_w, th_w, ph_w, g_b, th_b, ph_b, w_w);

    // fused g/theta/phi conv (+ z-maxpool for g, phi)
    gemm_kernel<256, 384, 0><<<dim3(3, 256, BATCH), 256>>>(x, nullptr);

    // attention per (b,w,h) group
    attn_kernel<<<BATCH * 1024, 128>>>();

    // W conv: CI -> C  (X = d_y, resolved INSIDE device code)
    gemm_kernel<128, 256, 1><<<dim3(2, 256, BATCH), 256>>>(nullptr, w_b);

    // batchnorm (training-mode batch stats) + residual
    bn_stats<<<256, 256>>>(gamma, beta);
    bn_apply<<<32768, 256>>>(x, out);
}

// round 6
// speedup vs baseline: 1.5541x; 1.5541x over previous
#include <cuda_runtime.h>
#include <cuda_bf16.h>
#include <math.h>
#include <stdint.h>

#define S_DIM   32768
#define SH_DIM  16384
#define BATCH   4

// ---------------- device-global scratch (no runtime allocation) ----------------
__device__ __align__(16) __nv_bfloat16 d_W1h[384 * 256], d_W1l[384 * 256];  // [g;theta;phi] [o][c]
__device__ __align__(16) __nv_bfloat16 d_W2h[256 * 128], d_W2l[256 * 128];  // w_w [co][ci]
__device__ __align__(16) float d_Bs1[384];
__device__ __align__(16) __nv_bfloat16 d_xth[(size_t)BATCH * S_DIM * 256];  // x^T hi [b][s][c]
__device__ __align__(16) __nv_bfloat16 d_xtl[(size_t)BATCH * S_DIM * 256];  // x^T lo
__device__ __align__(16) float d_th [(size_t)BATCH * 128 * S_DIM];          // theta [b][ci][s]
__device__ __align__(16) float d_gp [(size_t)BATCH * 128 * SH_DIM];         // g pooled
__device__ __align__(16) float d_php[(size_t)BATCH * 128 * SH_DIM];         // phi pooled
__device__ __align__(16) __nv_bfloat16 d_yth[(size_t)BATCH * S_DIM * 128];  // y^T hi [b][s][ci]
__device__ __align__(16) __nv_bfloat16 d_ytl[(size_t)BATCH * S_DIM * 128];  // y^T lo
__device__ __align__(16) float d_wy [(size_t)BATCH * 256 * S_DIM];
__device__ float d_scale[256], d_shift[256];

// ---------------- helpers -------------------------------------------------------
__device__ __forceinline__ uint32_t smem_u32(const void* p) {
    uint32_t a;
    asm("{ .reg .u64 t; cvta.to.shared.u64 t, %1; cvt.u32.u64 %0, t; }" : "=r"(a) : "l"(p));
    return a;
}
__device__ __forceinline__ void ldsm_x4(uint32_t* r, uint32_t addr) {
    asm volatile("ldmatrix.sync.aligned.m8n8.x4.shared.b16 {%0,%1,%2,%3}, [%4];"
                 : "=r"(r[0]), "=r"(r[1]), "=r"(r[2]), "=r"(r[3]) : "r"(addr));
}
__device__ __forceinline__ void ldsm_x2(uint32_t* r, uint32_t addr) {
    asm volatile("ldmatrix.sync.aligned.m8n8.x2.shared.b16 {%0,%1}, [%2];"
                 : "=r"(r[0]), "=r"(r[1]) : "r"(addr));
}
__device__ __forceinline__ void mma16816(float* d, const uint32_t* a, const uint32_t* b) {
    asm volatile(
        "mma.sync.aligned.m16n8k16.row.col.f32.bf16.bf16.f32 "
        "{%0,%1,%2,%3}, {%4,%5,%6,%7}, {%8,%9}, {%0,%1,%2,%3};"
        : "+f"(d[0]), "+f"(d[1]), "+f"(d[2]), "+f"(d[3])
        : "r"(a[0]), "r"(a[1]), "r"(a[2]), "r"(a[3]), "r"(b[0]), "r"(b[1]));
}
__device__ __forceinline__ void bsplit(float v, __nv_bfloat16& h, __nv_bfloat16& l) {
    h = __float2bfloat16(v);
    l = __float2bfloat16(v - __bfloat162float(h));
}

// ---------------- prep: weight splits + stacked biases ---------------------------
__global__ void prep_kernel(const float* __restrict__ g_w,  const float* __restrict__ th_w,
                            const float* __restrict__ ph_w, const float* __restrict__ g_b,
                            const float* __restrict__ th_b, const float* __restrict__ ph_b,
                            const float* __restrict__ w_w) {
    int i = blockIdx.x * 256 + threadIdx.x;
    if (i < 98304) {                 // W1 stacked [o=384][c=256] row-major
        int o = i >> 8;
        const float* src = (o < 128) ? g_w : (o < 256 ? th_w : ph_w);
        float v = src[(o & 127) * 256 + (i & 255)];
        bsplit(v, d_W1h[i], d_W1l[i]);
    }
    if (i < 32768) {                 // W2 [co=256][ci=128] row-major
        bsplit(w_w[i], d_W2h[i], d_W2l[i]);
    }
    if (i < 384) {
        d_Bs1[i] = (i < 128) ? g_b[i] : (i < 256 ? th_b[i - 128] : ph_b[i - 256]);
    }
}

// ---------------- transpose + split x: [b][c][s] f32 -> [b][s][c] bf16 hi/lo -----
__global__ void __launch_bounds__(256) split_x(const float* __restrict__ x) {
    __shared__ float t[32][33];
    const int s0 = blockIdx.x * 32, c0 = blockIdx.y * 32, b = blockIdx.z;
    const int ls = threadIdx.x & 31, lc = threadIdx.x >> 5;
#pragma unroll
    for (int i = 0; i < 4; i++) {
        int c = lc + i * 8;
        t[c][ls] = x[((size_t)(b * 256 + c0 + c)) * S_DIM + s0 + ls];
    }
    __syncthreads();
#pragma unroll
    for (int i = 0; i < 2; i++) {
        int idx = threadIdx.x + i * 256;       // 512 bf162-pairs: 32 s-rows x 16 c-pairs
        int s = idx >> 4, k = idx & 15;
        float v0 = t[2 * k][s], v1 = t[2 * k + 1][s];
        __nv_bfloat16 h0, l0, h1, l1;
        bsplit(v0, h0, l0); bsplit(v1, h1, l1);
        size_t o = ((size_t)b * S_DIM + s0 + s) * 256 + c0 + 2 * k;
        __nv_bfloat162 hv; hv.x = h0; hv.y = h1;
        __nv_bfloat162 lv; lv.x = l0; lv.y = l1;
        *(__nv_bfloat162*)(d_xth + o) = hv;
        *(__nv_bfloat162*)(d_xtl + o) = lv;
    }
}

// ---------------- tile loader: [128 rows x 64 bf16] gmem -> SW128 swizzled smem --
// byte = row*128 + j*16; swizzle byte ^ ((byte>>3)&0x70). 256 threads, 4 uint4 each.
__device__ __forceinline__ void load_tile(const __nv_bfloat16* __restrict__ src, int ld,
                                          unsigned char* sm, int tid) {
#pragma unroll
    for (int it = 0; it < 4; it++) {
        int idx = tid + it * 256;
        int row = idx >> 3, j = idx & 7;
        uint4 v = *(const uint4*)(src + (size_t)row * ld + j * 8);
        uint32_t byte = (uint32_t)(row * 128 + j * 16);
        *(uint4*)(sm + (byte ^ ((byte >> 3) & 0x70))) = v;
    }
}

// ---------------- HMMA GEMM: D[o][s] = sum_c W[o][c] * Xt[s][c] -------------------
// bf16-split 3 passes (AhBh + AhBl + AlBh) in fp32 accumulators.
// Block 128o x 128s; 8 warps = 2(o) x 4(s); warp tile 64o x 32s; K-chunk 64.
// MODE 0: conv3 (KDIM=256): ot=0 g->pooled, 1 theta->full, 2 phi->pooled.
// MODE 1: wconv (KDIM=128): output d_wy + w_b bias.
template <int KDIM, int MODE>
__global__ void __launch_bounds__(256, 2) mma_gemm(const float* __restrict__ wb) {
    __shared__ __align__(128) unsigned char smA[16384];
    __shared__ __align__(128) unsigned char smB[16384];

    const int tid = threadIdx.x, lane = tid & 31, wid = tid >> 5;
    const int ot = blockIdx.x, st = blockIdx.y, b = blockIdx.z;
    const int s0 = st * 128;
    const int wo = wid & 1, ws = wid >> 1;

    const int ldA = MODE ? 128 : 256;
    const __nv_bfloat16* Ah = (MODE ? d_W2h : d_W1h) + (size_t)(ot * 128) * ldA;
    const __nv_bfloat16* Al = (MODE ? d_W2l : d_W1l) + (size_t)(ot * 128) * ldA;
    const __nv_bfloat16* Bh = (MODE ? d_yth : d_xth) + ((size_t)b * S_DIM + s0) * ldA;
    const __nv_bfloat16* Bl = (MODE ? d_ytl : d_xtl) + ((size_t)b * S_DIM + s0) * ldA;

    float acc[4][4][4];
#pragma unroll
    for (int i = 0; i < 4; i++)
#pragma unroll
        for (int j = 0; j < 4; j++)
#pragma unroll
            for (int k = 0; k < 4; k++) acc[i][j][k] = 0.f;

    const uint32_t aBase = smem_u32(smA), bBase = smem_u32(smB);
    // ldmatrix lane address components (standard m16n8k16 fragment layout)
    const int aRow = ((lane >> 3) & 1) * 8 + (lane & 7);  // sub 0/2: rows 0-7, sub 1/3: rows 8-15
    const int aK   = (lane >> 4) * 16;                    // subs 2,3: k+8 (=+16B)
    const int bRow = lane & 7;
    const int bK   = ((lane >> 3) & 1) * 16;

#pragma unroll 1
    for (int pass = 0; pass < 3; pass++) {
        const __nv_bfloat16* As = (pass == 2) ? Al : Ah;
        const __nv_bfloat16* Bs = (pass == 1) ? Bl : Bh;
#pragma unroll 1
        for (int kc = 0; kc < KDIM / 64; kc++) {
            __syncthreads();
            load_tile(As + kc * 64, ldA, smA, tid);
            load_tile(Bs + kc * 64, ldA, smB, tid);
            __syncthreads();
#pragma unroll
            for (int kk = 0; kk < 4; kk++) {     // 4 x k16 per chunk
                uint32_t af[4][4], bf[4][2];
#pragma unroll
                for (int fo = 0; fo < 4; fo++) {
                    uint32_t byte = (uint32_t)((wo * 64 + fo * 16 + aRow) * 128 + kk * 32 + aK);
                    ldsm_x4(af[fo], aBase + (byte ^ ((byte >> 3) & 0x70)));
                }
#pragma unroll
                for (int n8 = 0; n8 < 4; n8++) {
                    uint32_t byte = (uint32_t)((ws * 32 + n8 * 8 + bRow) * 128 + kk * 32 + bK);
                    ldsm_x2(bf[n8], bBase + (byte ^ ((byte >> 3) & 0x70)));
                }
#pragma unroll
                for (int fo = 0; fo < 4; fo++)
#pragma unroll
                    for (int n8 = 0; n8 < 4; n8++)
                        mma16816(acc[fo][n8], af[fo], bf[n8]);
            }
        }
    }

    // ---- epilogue straight from fragments ----
    // D frag: c0,c1 = (row=lane/4, col=2*(lane%3..)={2*(lane&3),+1}); c2,c3 = row+8.
    const int l4 = lane >> 2, l2 = (lane & 3) * 2;
#pragma unroll
    for (int fo = 0; fo < 4; fo++) {
        const int o_loc = wo * 64 + fo * 16 + l4;
        float bia0, bia1;
        if (MODE == 0) { bia0 = d_Bs1[ot * 128 + o_loc]; bia1 = d_Bs1[ot * 128 + o_loc + 8]; }
        else           { bia0 = wb[ot * 128 + o_loc];    bia1 = wb[ot * 128 + o_loc + 8]; }
#pragma unroll
        for (int n8 = 0; n8 < 4; n8++) {
            const int s = s0 + ws * 32 + n8 * 8 + l2;
            float c0 = acc[fo][n8][0], c1 = acc[fo][n8][1];
            float c2 = acc[fo][n8][2], c3 = acc[fo][n8][3];
            if (MODE == 1) {
                int o = ot * 128 + o_loc;
                *(float2*)&d_wy[((size_t)(b * 256 + o)) * S_DIM + s] =
                    make_float2(c0 + bia0, c1 + bia0);
                *(float2*)&d_wy[((size_t)(b * 256 + o + 8)) * S_DIM + s] =
                    make_float2(c2 + bia1, c3 + bia1);
            } else if (ot == 1) {          // theta: full z
                *(float2*)&d_th[((size_t)(b * 128 + o_loc)) * S_DIM + s] =
                    make_float2(c0 + bia0, c1 + bia0);
                *(float2*)&d_th[((size_t)(b * 128 + o_loc + 8)) * S_DIM + s] =
                    make_float2(c2 + bia1, c3 + bia1);
            } else {                       // g / phi: z-maxpool = fragment col pair
                float* dst = ot ? d_php : d_gp;
                int sp = ((s0 + ws * 32 + n8 * 8) >> 1) + (lane & 3);
                dst[((size_t)(b * 128 + o_loc)) * SH_DIM + sp]     = fmaxf(c0, c1) + bia0;
                dst[((size_t)(b * 128 + o_loc + 8)) * SH_DIM + sp] = fmaxf(c2, c3) + bia1;
            }
        }
    }
}

// ---------------- attention per (b,w,h): outputs y^T bf16 hi/lo -------------------
__global__ void __launch_bounds__(128) attn_kernel() {
    __shared__ float th_s[128 * 36];   // theta tile; reused as y stage
    __shared__ float ph_s[128 * 17];
    __shared__ float g_s [128 * 17];
    __shared__ float f_s [32 * 16];

    const int grp = blockIdx.x;
    const int b   = grp >> 10;
    const int wh  = grp & 1023;
    const int tid = threadIdx.x;

    {   // theta tile: 128 c-rows x 32 z
        const float* base = d_th + (size_t)(b * 128) * S_DIM + wh * 32;
        for (int i = tid; i < 1024; i += 128) {
            int c = i >> 3, q = i & 7;
            float4 v = *(const float4*)(base + (size_t)c * S_DIM + q * 4);
            *(float4*)&th_s[c * 36 + q * 4] = v;
        }
    }
    {   // pooled g / phi tiles: 128 c-rows x 16 y
        const float* gb = d_gp  + (size_t)(b * 128) * SH_DIM + wh * 16;
        const float* pb = d_php + (size_t)(b * 128) * SH_DIM + wh * 16;
        for (int i = tid; i < 512; i += 128) {
            int c = i >> 2, q = (i & 3) * 4;
            float4 gv = *(const float4*)(gb + (size_t)c * SH_DIM + q);
            float4 pv = *(const float4*)(pb + (size_t)c * SH_DIM + q);
            int o = c * 17 + q;
            g_s[o + 0] = gv.x; g_s[o + 1] = gv.y; g_s[o + 2] = gv.z; g_s[o + 3] = gv.w;
            ph_s[o + 0] = pv.x; ph_s[o + 1] = pv.y; ph_s[o + 2] = pv.z; ph_s[o + 3] = pv.w;
        }
    }
    __syncthreads();

    {   // f[z][y] = sum_c th[c][z] * ph[c][y]
        const int z = tid >> 2, y0 = (tid & 3) * 4;
        float fv0 = 0.f, fv1 = 0.f, fv2 = 0.f, fv3 = 0.f;
#pragma unroll 8
        for (int c = 0; c < 128; c++) {
            float t = th_s[c * 36 + z];
            fv0 += t * ph_s[c * 17 + y0 + 0];
            fv1 += t * ph_s[c * 17 + y0 + 1];
            fv2 += t * ph_s[c * 17 + y0 + 2];
            fv3 += t * ph_s[c * 17 + y0 + 3];
        }
        f_s[z * 16 + y0 + 0] = fv0;
        f_s[z * 16 + y0 + 1] = fv1;
        f_s[z * 16 + y0 + 2] = fv2;
        f_s[z * 16 + y0 + 3] = fv3;
    }
    __syncthreads();

    if (tid < 32) {   // softmax over y
        int z = tid;
        float mm = -1e30f;
#pragma unroll
        for (int y = 0; y < 16; y++) mm = fmaxf(mm, f_s[z * 16 + y]);
        float sum = 0.f;
#pragma unroll
        for (int y = 0; y < 16; y++) {
            float e = __expf(f_s[z * 16 + y] - mm);
            f_s[z * 16 + y] = e;
            sum += e;
        }
        float inv = 1.f / sum;
#pragma unroll
        for (int y = 0; y < 16; y++) f_s[z * 16 + y] *= inv;
    }
    __syncthreads();

    {   // y[c][z] = sum_y attn[z][y]*g[c][y]; stage into th_s
        const int c = tid;
        float yv[32];
#pragma unroll
        for (int z = 0; z < 32; z++) {
            float a = 0.f;
#pragma unroll
            for (int y = 0; y < 16; y++) a += f_s[z * 16 + y] * g_s[c * 17 + y];
            yv[z] = a;
        }
#pragma unroll
        for (int q = 0; q < 8; q++)
            *(float4*)&th_s[c * 36 + q * 4] =
                make_float4(yv[4 * q], yv[4 * q + 1], yv[4 * q + 2], yv[4 * q + 3]);
    }
    __syncthreads();

    {   // transposed bf16 hi/lo writeout: y^T[s][c]
        for (int i = 0; i < 16; i++) {
            int idx = tid + i * 128;
            int z = idx >> 6, k = idx & 63;
            float v0 = th_s[(2 * k) * 36 + z];
            float v1 = th_s[(2 * k + 1) * 36 + z];
            __nv_bfloat16 h0, l0, h1, l1;
            bsplit(v0, h0, l0); bsplit(v1, h1, l1);
            size_t o = ((size_t)b * S_DIM + wh * 32 + z) * 128 + 2 * k;
            __nv_bfloat162 hv; hv.x = h0; hv.y = h1;
            __nv_bfloat162 lv; lv.x = l0; lv.y = l1;
            *(__nv_bfloat162*)(d_yth + o) = hv;
            *(__nv_bfloat162*)(d_ytl + o) = lv;
        }
    }
}

// ---------------- BN stats --------------------------------------------------------
__global__ void __launch_bounds__(256) bn_stats(const float* __restrict__ gamma,
                                                const float* __restrict__ beta) {
    const int c = blockIdx.x;
    const int tid = threadIdx.x;
    float s = 0.f, s2 = 0.f;
    for (int i = tid; i < (BATCH * S_DIM) / 4; i += 256) {
        int e  = i * 4;
        int b  = e >> 15;
        int sp = e & (S_DIM - 1);
        float4 v = *(const float4*)&d_wy[((size_t)(b * 256 + c)) * S_DIM + sp];
        s  += v.x + v.y + v.z + v.w;
        s2 += v.x * v.x + v.y * v.y + v.z * v.z + v.w * v.w;
    }
    __shared__ float sh[256], sh2[256];
    sh[tid] = s; sh2[tid] = s2;
    __syncthreads();
    for (int off = 128; off > 0; off >>= 1) {
        if (tid < off) { sh[tid] += sh[tid + off]; sh2[tid] += sh2[tid + off]; }
        __syncthreads();
    }
    if (tid == 0) {
        float n = (float)(BATCH * S_DIM);
        float mean = sh[0] / n;
        float var  = sh2[0] / n - mean * mean;
        float inv  = rsqrtf(var + 1e-5f);
        float sc   = gamma[c] * inv;
        d_scale[c] = sc;
        d_shift[c] = beta[c] - mean * sc;
    }
}

// ---------------- BN apply + residual ----------------------------------------------
__global__ void __launch_bounds__(256) bn_apply(const float* __restrict__ x,
                                                float* __restrict__ out) {
    size_t i = (size_t)blockIdx.x * 256 + threadIdx.x;
    size_t e = i * 4;
    int c = (int)((e >> 15) & 255);
    float4 w  = *(const float4*)&d_wy[e];
    float4 xv = *(const float4*)(x + e);
    float sc = d_scale[c], sf = d_shift[c];
    float4 o;
    o.x = w.x * sc + sf + xv.x;
    o.y = w.y * sc + sf + xv.y;
    o.z = w.z * sc + sf + xv.z;
    o.w = w.w * sc + sf + xv.w;
    *(float4*)(out + e) = o;
}

// ---------------- launch ------------------------------------------------------------
extern "C" void kernel_launch(void* const* d_in, const int* in_sizes, int n_in,
                              void* d_out, int out_size) {
    const float* x     = (const float*)d_in[0];
    const float* g_w   = (const float*)d_in[1];
    const float* g_b   = (const float*)d_in[2];
    const float* th_w  = (const float*)d_in[3];
    const float* th_b  = (const float*)d_in[4];
    const float* ph_w  = (const float*)d_in[5];
    const float* ph_b  = (const float*)d_in[6];
    const float* w_w   = (const float*)d_in[7];
    const float* w_b   = (const float*)d_in[8];
    const float* gamma = (const float*)d_in[9];
    const float* beta  = (const float*)d_in[10];
    float* out = (float*)d_out;

    prep_kernel<<<384, 256>>>(g_w, th_w, ph_w, g_b, th_b, ph_b, w_w);
    split_x<<<dim3(1024, 8, BATCH), 256>>>(x);

    // fused g/theta/phi conv via HMMA (+ z-maxpool for g, phi)
    mma_gemm<256, 0><<<dim3(3, 256, BATCH), 256>>>(nullptr);

    attn_kernel<<<BATCH * 1024, 128>>>();

    // W conv via HMMA
    mma_gemm<128, 1><<<dim3(2, 256, BATCH), 256>>>(w_b);

    bn_stats<<<256, 256>>>(gamma, beta);
    bn_apply<<<32768, 256>>>(x, out);
}